// round 1
// baseline (speedup 1.0000x reference)
#include <cuda_runtime.h>

constexpr int CN = 384;
constexpr int NHEAD = 4;
constexpr int HDIM = 96;
constexpr int HH = 64;
constexpr int WW = 128;
constexpr int HW = HH * WW;   // 8192
constexpr int BB = 8;

// Scratch (device globals: allocation-free, harness-legal)
__device__ float g_q[BB * CN * HW];        // Q projection
__device__ float g_kv[BB * 2 * CN * HW];   // K (ch 0..383) + V (ch 384..767)
__device__ float g_ao[BB * CN * HW];       // attention output
__device__ float g_o2[BB * CN * HW];       // O projection
__device__ float g_psum[BB * CN];
__device__ float g_psq[BB * CN];
__device__ float g_scale[CN];
__device__ float g_shift[CN];

// ---------------------------------------------------------------------------
// Generic 128x128x8 SGEMM over channel dim:
//   Y[(bz*M + m)*HW + n] = epilogue( sum_c A[m][c] * X[(bz*Cin + c)*HW + n] + bias[m] )
// A rows split across (A0 | A1) at Msplit (for stacked wk/wv), X channels split
// across (X0 | X1) at Ksplit (for concat(feat_self, out2)).
// MODE 0: plain store. MODE 1: gate epilogue  Y = fs + sigmoid(v) * o2.
// ---------------------------------------------------------------------------
template <int MODE>
__global__ __launch_bounds__(256, 2)
void gemm_k(const float* __restrict__ A0, const float* __restrict__ A1,
            int Msplit, int lda,
            const float* __restrict__ bias0, const float* __restrict__ bias1,
            const float* __restrict__ X0, const float* __restrict__ X1,
            int Ksplit, int M, int K,
            float* __restrict__ Y,
            const float* __restrict__ fs, const float* __restrict__ o2)
{
    __shared__ float As[8][128];
    __shared__ float Bs[8][128];
    const int tid = threadIdx.x;
    const int tx = tid & 15;
    const int ty = tid >> 4;
    const int row0 = blockIdx.y * 128;
    const int col0 = blockIdx.x * 128;
    const int bz = blockIdx.z;

    float acc[8][8];
#pragma unroll
    for (int i = 0; i < 8; i++)
#pragma unroll
        for (int j = 0; j < 8; j++) acc[i][j] = 0.f;

    const int am = tid >> 1;        // 0..127 (A row within tile)
    const int ak = (tid & 1) * 4;   // 0 or 4 (A k sub-offset, float4)
    const int mg = row0 + am;
    const float* aptr = (mg < Msplit) ? (A0 + (size_t)mg * lda)
                                      : (A1 + (size_t)(mg - Msplit) * lda);
    const int bk = tid >> 5;        // 0..7  (X k row)
    const int bp = (tid & 31) * 4;  // 0..124 (X col, float4)
    const int C1 = K - Ksplit;

    for (int k0 = 0; k0 < K; k0 += 8) {
        float4 av = *(const float4*)(aptr + k0 + ak);
        const int cg = k0 + bk;
        const float* xptr = (cg < Ksplit)
            ? (X0 + ((size_t)bz * Ksplit + cg) * HW)
            : (X1 + ((size_t)bz * C1 + (cg - Ksplit)) * HW);
        float4 bv = *(const float4*)(xptr + col0 + bp);
        As[ak + 0][am] = av.x;
        As[ak + 1][am] = av.y;
        As[ak + 2][am] = av.z;
        As[ak + 3][am] = av.w;
        *(float4*)&Bs[bk][bp] = bv;
        __syncthreads();
#pragma unroll
        for (int kk = 0; kk < 8; kk++) {
            float a[8], b[8];
#pragma unroll
            for (int i = 0; i < 8; i++) a[i] = As[kk][ty + 16 * i];
#pragma unroll
            for (int j = 0; j < 8; j++) b[j] = Bs[kk][tx + 16 * j];
#pragma unroll
            for (int i = 0; i < 8; i++)
#pragma unroll
                for (int j = 0; j < 8; j++)
                    acc[i][j] = fmaf(a[i], b[j], acc[i][j]);
        }
        __syncthreads();
    }

#pragma unroll
    for (int i = 0; i < 8; i++) {
        const int m = row0 + ty + 16 * i;
        const float bias = (m < Msplit) ? bias0[m] : bias1[m - Msplit];
#pragma unroll
        for (int j = 0; j < 8; j++) {
            const int n = col0 + tx + 16 * j;
            float v = acc[i][j] + bias;
            const size_t idx = ((size_t)bz * M + m) * HW + n;
            if (MODE == 0) {
                Y[idx] = v;
            } else {
                const float g = 1.f / (1.f + __expf(-v));
                Y[idx] = fs[idx] + g * o2[idx];
            }
        }
    }
}

// ---------------------------------------------------------------------------
// Epipolar attention: one block per (b, head, h).
//   S[w][wp] = (1/sqrt(HD)) * sum_cc Q[cc][w] * K[cc][wp]   (stored S[wp][w])
//   P = softmax over wp;  out[cc][w] = sum_wp V[cc][wp] * P[wp][w]
// smem: Q 48KB + K/V 48KB + S 64KB = 160KB dynamic.
// ---------------------------------------------------------------------------
__global__ __launch_bounds__(256, 1)
void attn_k(const float* __restrict__ q, const float* __restrict__ kv,
            float* __restrict__ ao)
{
    extern __shared__ float sm[];
    float* Qs = sm;                     // [96][128]
    float* Ks = sm + HDIM * WW;         // [96][128] (K, then reused for V)
    float* Ss = sm + 2 * HDIM * WW;     // [128][128]  S[wp][w]
    const int h = blockIdx.x, n = blockIdx.y, b = blockIdx.z;
    const int tid = threadIdx.x;

    const size_t qbase = (((size_t)b * CN + n * HDIM) * HH + h) * WW;
    const size_t kbase = (((size_t)b * 2 * CN + n * HDIM) * HH + h) * WW;
    const size_t vbase = kbase + (size_t)CN * HW;

    {   // load Q and K tiles (96 rows x 32 float4)
        const int lane = tid & 31;
        const int r0 = tid >> 5;
#pragma unroll
        for (int it = 0; it < 12; it++) {
            const int cc = r0 + it * 8;
            *(float4*)&Qs[cc * WW + lane * 4] =
                *(const float4*)(q + qbase + (size_t)cc * HW + lane * 4);
            *(float4*)&Ks[cc * WW + lane * 4] =
                *(const float4*)(kv + kbase + (size_t)cc * HW + lane * 4);
        }
    }
    __syncthreads();

    const int tx = tid & 15, ty = tid >> 4;
    {   // GEMM1: S = scale * K^T(wp,cc) . Q(cc,w), 8x8 per thread
        float acc[8][8];
#pragma unroll
        for (int j = 0; j < 8; j++)
#pragma unroll
            for (int i = 0; i < 8; i++) acc[j][i] = 0.f;
#pragma unroll 4
        for (int cc = 0; cc < HDIM; cc++) {
            float qf[8], kf[8];
#pragma unroll
            for (int i = 0; i < 8; i++) qf[i] = Qs[cc * WW + tx + 16 * i];
#pragma unroll
            for (int j = 0; j < 8; j++) kf[j] = Ks[cc * WW + ty + 16 * j];
#pragma unroll
            for (int j = 0; j < 8; j++)
#pragma unroll
                for (int i = 0; i < 8; i++)
                    acc[j][i] = fmaf(kf[j], qf[i], acc[j][i]);
        }
        const float scale = 0.10206207261596575f;  // 1/sqrt(96)
#pragma unroll
        for (int j = 0; j < 8; j++)
#pragma unroll
            for (int i = 0; i < 8; i++)
                Ss[(ty + 16 * j) * WW + tx + 16 * i] = acc[j][i] * scale;
    }
    __syncthreads();

    // softmax (threads 0..127, one column w each; stride-128 reads are
    // lane-consecutive -> conflict-free) overlapped with V load (threads 128..255)
    if (tid < WW) {
        const int w = tid;
        float mx = -1e30f;
#pragma unroll 8
        for (int wp = 0; wp < WW; wp++) mx = fmaxf(mx, Ss[wp * WW + w]);
        float s = 0.f;
#pragma unroll 8
        for (int wp = 0; wp < WW; wp++) {
            const float e = __expf(Ss[wp * WW + w] - mx);
            Ss[wp * WW + w] = e;
            s += e;
        }
        const float inv = 1.f / s;
#pragma unroll 8
        for (int wp = 0; wp < WW; wp++) Ss[wp * WW + w] *= inv;
    } else {
        const int t = tid - 128;
        const int lane = t & 31;
        const int r0 = t >> 5;
#pragma unroll
        for (int it = 0; it < 24; it++) {
            const int cc = r0 + it * 4;
            *(float4*)&Ks[cc * WW + lane * 4] =
                *(const float4*)(kv + vbase + (size_t)cc * HW + lane * 4);
        }
    }
    __syncthreads();

    {   // GEMM2: out[cc][w] = V[cc][:] . P[:][w], 6x8 per thread
        float acc2[6][8];
#pragma unroll
        for (int jc = 0; jc < 6; jc++)
#pragma unroll
            for (int i = 0; i < 8; i++) acc2[jc][i] = 0.f;
#pragma unroll 4
        for (int wp = 0; wp < WW; wp++) {
            float vf[6], pf[8];
#pragma unroll
            for (int jc = 0; jc < 6; jc++) vf[jc] = Ks[(ty + 16 * jc) * WW + wp];
#pragma unroll
            for (int i = 0; i < 8; i++) pf[i] = Ss[wp * WW + tx + 16 * i];
#pragma unroll
            for (int jc = 0; jc < 6; jc++)
#pragma unroll
                for (int i = 0; i < 8; i++)
                    acc2[jc][i] = fmaf(vf[jc], pf[i], acc2[jc][i]);
        }
#pragma unroll
        for (int jc = 0; jc < 6; jc++) {
            const int cc = ty + 16 * jc;
#pragma unroll
            for (int i = 0; i < 8; i++)
                ao[qbase + (size_t)cc * HW + tx + 16 * i] = acc2[jc][i];
        }
    }
}

// ---------------------------------------------------------------------------
// BatchNorm (training-mode batch stats), 3 stages, no atomics
// ---------------------------------------------------------------------------
__global__ __launch_bounds__(256)
void bnstats_k(const float* __restrict__ y)
{
    const int bc = blockIdx.x;  // b*CN + c
    const float4* p = (const float4*)(y + (size_t)bc * HW);
    const int tid = threadIdx.x;
    float s = 0.f, sq = 0.f;
#pragma unroll
    for (int it = 0; it < 8; it++) {
        const float4 v = p[tid + it * 256];
        s += v.x + v.y + v.z + v.w;
        sq += v.x * v.x + v.y * v.y + v.z * v.z + v.w * v.w;
    }
#pragma unroll
    for (int o = 16; o > 0; o >>= 1) {
        s += __shfl_down_sync(0xffffffffu, s, o);
        sq += __shfl_down_sync(0xffffffffu, sq, o);
    }
    __shared__ float ss[8], sqq[8];
    if ((tid & 31) == 0) { ss[tid >> 5] = s; sqq[tid >> 5] = sq; }
    __syncthreads();
    if (tid == 0) {
        float ts = 0.f, tq = 0.f;
#pragma unroll
        for (int i = 0; i < 8; i++) { ts += ss[i]; tq += sqq[i]; }
        g_psum[bc] = ts;
        g_psq[bc] = tq;
    }
}

__global__ void bnfin_k(const float* __restrict__ gamma,
                        const float* __restrict__ beta)
{
    const int c = threadIdx.x;
    float s = 0.f, sq = 0.f;
#pragma unroll
    for (int b = 0; b < BB; b++) { s += g_psum[b * CN + c]; sq += g_psq[b * CN + c]; }
    const float invN = 1.f / (float)(BB * HW);
    const float mean = s * invN;
    const float var = sq * invN - mean * mean;
    const float inv = rsqrtf(var + 1e-5f);
    const float sc = gamma[c] * inv;
    g_scale[c] = sc;
    g_shift[c] = beta[c] - mean * sc;
}

__global__ void bnapply_k(float* __restrict__ y)
{
    const size_t i = ((size_t)blockIdx.x * 256 + threadIdx.x) * 4;
    const int c = (int)((i >> 13) % CN);   // i / 8192 -> (b*CN + c)
    float4 v = *(float4*)(y + i);
    const float sc = g_scale[c], sh = g_shift[c];
    v.x = v.x * sc + sh;
    v.y = v.y * sc + sh;
    v.z = v.z * sc + sh;
    v.w = v.w * sc + sh;
    *(float4*)(y + i) = v;
}

// ---------------------------------------------------------------------------
extern "C" void kernel_launch(void* const* d_in, const int* in_sizes, int n_in,
                              void* d_out, int out_size)
{
    (void)in_sizes; (void)n_in; (void)out_size;
    const float* fs    = (const float*)d_in[0];
    const float* fo    = (const float*)d_in[1];
    const float* wq    = (const float*)d_in[2];
    const float* bq    = (const float*)d_in[3];
    const float* wk    = (const float*)d_in[4];
    const float* bk    = (const float*)d_in[5];
    const float* wv    = (const float*)d_in[6];
    const float* bv    = (const float*)d_in[7];
    const float* wo    = (const float*)d_in[8];
    const float* bo    = (const float*)d_in[9];
    const float* wg    = (const float*)d_in[10];
    const float* bg    = (const float*)d_in[11];
    const float* gamma = (const float*)d_in[12];
    const float* beta  = (const float*)d_in[13];
    float* out = (float*)d_out;

    float *q, *kvb, *ao, *o2;
    cudaGetSymbolAddress((void**)&q,   g_q);
    cudaGetSymbolAddress((void**)&kvb, g_kv);
    cudaGetSymbolAddress((void**)&ao,  g_ao);
    cudaGetSymbolAddress((void**)&o2,  g_o2);

    const int ATTN_SMEM = (2 * HDIM * WW + WW * WW) * (int)sizeof(float); // 163840
    cudaFuncSetAttribute(attn_k, cudaFuncAttributeMaxDynamicSharedMemorySize, ATTN_SMEM);

    const dim3 blk(256);
    // Q = wq @ feat_self + bq
    gemm_k<0><<<dim3(64, 3, 8), blk>>>(wq, wq, CN, CN, bq, bq,
                                       fs, fs, CN, CN, CN, q, nullptr, nullptr);
    // [K;V] = [wk;wv] @ feat_other + [bk;bv]
    gemm_k<0><<<dim3(64, 6, 8), blk>>>(wk, wv, CN, CN, bk, bv,
                                       fo, fo, CN, 2 * CN, CN, kvb, nullptr, nullptr);
    // epipolar attention per (h, head, b)
    attn_k<<<dim3(HH, NHEAD, BB), blk, ATTN_SMEM>>>(q, kvb, ao);
    // out2 = wo @ attn_out + bo
    gemm_k<0><<<dim3(64, 3, 8), blk>>>(wo, wo, CN, CN, bo, bo,
                                       ao, ao, CN, CN, CN, o2, nullptr, nullptr);
    // fused = fs + sigmoid(wg @ [fs; out2] + bg) * out2  -> d_out
    gemm_k<1><<<dim3(64, 3, 8), blk>>>(wg, wg, CN, 2 * CN, bg, bg,
                                       fs, o2, CN, CN, 2 * CN, out, fs, o2);
    // BatchNorm
    bnstats_k<<<BB * CN, 256>>>(out);
    bnfin_k<<<1, CN>>>(gamma, beta);
    bnapply_k<<<BB * CN * HW / 1024, 256>>>(out);
}

// round 2
// speedup vs baseline: 2.3942x; 2.3942x over previous
#include <cuda_runtime.h>
#include <cstdint>

constexpr int CN = 384;
constexpr int NHEAD = 4;
constexpr int HDIM = 96;
constexpr int HH = 64;
constexpr int WW = 128;
constexpr int HW = HH * WW;   // 8192
constexpr int BB = 8;

// Scratch (device globals: allocation-free, harness-legal)
__device__ float g_q[BB * CN * HW];        // Q projection
__device__ float g_kv[BB * 2 * CN * HW];   // K (ch 0..383) + V (ch 384..767)
__device__ float g_ao[BB * CN * HW];       // attention output
__device__ float g_o2[BB * CN * HW];       // O projection
__device__ float g_psum[BB * CN];
__device__ float g_psq[BB * CN];
__device__ float g_scale[CN];
__device__ float g_shift[CN];

__device__ __forceinline__ float to_tf32(float x) {
    uint32_t u;
    asm("cvt.rna.tf32.f32 %0, %1;" : "=r"(u) : "f"(x));
    return __uint_as_float(u);
}

__device__ __forceinline__ void mma_tf32(float4& d, const uint32_t a[4], const uint32_t b[2]) {
    asm volatile(
        "mma.sync.aligned.m16n8k8.row.col.f32.tf32.tf32.f32 "
        "{%0,%1,%2,%3}, {%4,%5,%6,%7}, {%8,%9}, {%0,%1,%2,%3};\n"
        : "+f"(d.x), "+f"(d.y), "+f"(d.z), "+f"(d.w)
        : "r"(a[0]), "r"(a[1]), "r"(a[2]), "r"(a[3]), "r"(b[0]), "r"(b[1]));
}

// ---------------------------------------------------------------------------
// Tensor-core (tf32 mma.sync) 128x128xK GEMM over channel dim:
//   Y[(bz*M + m)*HW + n] = epilogue( sum_c A[m][c] * X[(bz*Cin + c)*HW + n] + bias[m] )
// A rows split (A0|A1) at Msplit (stacked wk/wv); X channels split (X0|X1) at
// Ksplit (concat(feat_self, out2)). MODE 0: plain store. MODE 1: gate epilogue.
// 8 warps in 2(M)x4(N): warp tile 64x32, thread accum 4x4 m16n8 tiles.
// ---------------------------------------------------------------------------
constexpr int APAD = 20;    // As row stride (floats): conflict-free frag loads
constexpr int BPAD = 136;   // Bs row stride (floats): conflict-free frag loads

template <int MODE>
__global__ __launch_bounds__(256, 2)
void gemm_t(const float* __restrict__ A0, const float* __restrict__ A1,
            int Msplit, int lda,
            const float* __restrict__ bias0, const float* __restrict__ bias1,
            const float* __restrict__ X0, const float* __restrict__ X1,
            int Ksplit, int M, int K,
            float* __restrict__ Y,
            const float* __restrict__ fs, const float* __restrict__ o2)
{
    __shared__ float As[2][128 * APAD];
    __shared__ float Bs[2][16 * BPAD];

    const int tid = threadIdx.x;
    const int lane = tid & 31;
    const int warp = tid >> 5;
    const int group = lane >> 2;   // 0..7
    const int tig = lane & 3;      // 0..3
    const int wm = warp & 1;       // M warp coord (0..1)
    const int wn = warp >> 1;      // N warp coord (0..3)
    const int row0 = blockIdx.y * 128;
    const int col0 = blockIdx.x * 128;
    const int bz = blockIdx.z;
    const int C1 = K - Ksplit;

    // --- gmem staging maps ---
    const int m_ld = tid >> 1;          // A row within tile
    const int kq = (tid & 1) * 8;       // A k sub-offset
    const int mg = row0 + m_ld;
    const float* aptr = (mg < Msplit) ? (A0 + (size_t)mg * lda)
                                      : (A1 + (size_t)(mg - Msplit) * lda);
    const int kb0 = tid >> 5;           // B k rows: kb0 and kb0+8
    const int nq = (lane) * 4;          // B col (float4)

    float4 acc[4][4];
#pragma unroll
    for (int i = 0; i < 4; i++)
#pragma unroll
        for (int j = 0; j < 4; j++) acc[i][j] = make_float4(0.f, 0.f, 0.f, 0.f);

    const int iters = K >> 4;

    // ---- prologue: load tile 0 into buffer 0 ----
    {
        float4 a0 = *(const float4*)(aptr + kq);
        float4 a1 = *(const float4*)(aptr + kq + 4);
        const float* xp0 = (kb0 < Ksplit) ? (X0 + ((size_t)bz * Ksplit + kb0) * HW)
                                          : (X1 + ((size_t)bz * C1 + (kb0 - Ksplit)) * HW);
        const int kb1 = kb0 + 8;
        const float* xp1 = (kb1 < Ksplit) ? (X0 + ((size_t)bz * Ksplit + kb1) * HW)
                                          : (X1 + ((size_t)bz * C1 + (kb1 - Ksplit)) * HW);
        float4 b0 = *(const float4*)(xp0 + col0 + nq);
        float4 b1 = *(const float4*)(xp1 + col0 + nq);
        float* ap = &As[0][m_ld * APAD + kq];
        ap[0] = to_tf32(a0.x); ap[1] = to_tf32(a0.y); ap[2] = to_tf32(a0.z); ap[3] = to_tf32(a0.w);
        ap[4] = to_tf32(a1.x); ap[5] = to_tf32(a1.y); ap[6] = to_tf32(a1.z); ap[7] = to_tf32(a1.w);
        float* bp0 = &Bs[0][kb0 * BPAD + nq];
        bp0[0] = to_tf32(b0.x); bp0[1] = to_tf32(b0.y); bp0[2] = to_tf32(b0.z); bp0[3] = to_tf32(b0.w);
        float* bp1 = &Bs[0][kb1 * BPAD + nq];
        bp1[0] = to_tf32(b1.x); bp1[1] = to_tf32(b1.y); bp1[2] = to_tf32(b1.z); bp1[3] = to_tf32(b1.w);
    }
    __syncthreads();

    for (int it = 0; it < iters; it++) {
        const int buf = it & 1;
        // prefetch next tile into registers
        float4 pa0, pa1, pb0, pb1;
        const bool more = (it + 1 < iters);
        if (more) {
            const int k0 = (it + 1) << 4;
            pa0 = *(const float4*)(aptr + k0 + kq);
            pa1 = *(const float4*)(aptr + k0 + kq + 4);
            const int cg0 = k0 + kb0;
            const float* xp0 = (cg0 < Ksplit) ? (X0 + ((size_t)bz * Ksplit + cg0) * HW)
                                              : (X1 + ((size_t)bz * C1 + (cg0 - Ksplit)) * HW);
            const int cg1 = cg0 + 8;
            const float* xp1 = (cg1 < Ksplit) ? (X0 + ((size_t)bz * Ksplit + cg1) * HW)
                                              : (X1 + ((size_t)bz * C1 + (cg1 - Ksplit)) * HW);
            pb0 = *(const float4*)(xp0 + col0 + nq);
            pb1 = *(const float4*)(xp1 + col0 + nq);
        }

        // compute on current buffer: two k8 steps
        const float* Ab = As[buf];
        const float* Bb = Bs[buf];
#pragma unroll
        for (int kk = 0; kk < 16; kk += 8) {
            uint32_t a[4][4], b[4][2];
#pragma unroll
            for (int mt = 0; mt < 4; mt++) {
                const int r = wm * 64 + mt * 16 + group;
                a[mt][0] = __float_as_uint(Ab[r * APAD + kk + tig]);
                a[mt][1] = __float_as_uint(Ab[(r + 8) * APAD + kk + tig]);
                a[mt][2] = __float_as_uint(Ab[r * APAD + kk + tig + 4]);
                a[mt][3] = __float_as_uint(Ab[(r + 8) * APAD + kk + tig + 4]);
            }
#pragma unroll
            for (int nt = 0; nt < 4; nt++) {
                const int c = wn * 32 + nt * 8 + group;
                b[nt][0] = __float_as_uint(Bb[(kk + tig) * BPAD + c]);
                b[nt][1] = __float_as_uint(Bb[(kk + tig + 4) * BPAD + c]);
            }
#pragma unroll
            for (int mt = 0; mt < 4; mt++)
#pragma unroll
                for (int nt = 0; nt < 4; nt++)
                    mma_tf32(acc[mt][nt], a[mt], b[nt]);
        }

        // store prefetched tile into other buffer
        if (more) {
            const int nb = buf ^ 1;
            float* ap = &As[nb][m_ld * APAD + kq];
            ap[0] = to_tf32(pa0.x); ap[1] = to_tf32(pa0.y); ap[2] = to_tf32(pa0.z); ap[3] = to_tf32(pa0.w);
            ap[4] = to_tf32(pa1.x); ap[5] = to_tf32(pa1.y); ap[6] = to_tf32(pa1.z); ap[7] = to_tf32(pa1.w);
            float* bp0 = &Bs[nb][kb0 * BPAD + nq];
            bp0[0] = to_tf32(pb0.x); bp0[1] = to_tf32(pb0.y); bp0[2] = to_tf32(pb0.z); bp0[3] = to_tf32(pb0.w);
            float* bp1 = &Bs[nb][(kb0 + 8) * BPAD + nq];
            bp1[0] = to_tf32(pb1.x); bp1[1] = to_tf32(pb1.y); bp1[2] = to_tf32(pb1.z); bp1[3] = to_tf32(pb1.w);
        }
        __syncthreads();
    }

    // ---- epilogue ----
#pragma unroll
    for (int mt = 0; mt < 4; mt++) {
        const int r0 = row0 + wm * 64 + mt * 16 + group;
        const int r1 = r0 + 8;
        const float bia0 = (r0 < Msplit) ? bias0[r0] : bias1[r0 - Msplit];
        const float bia1 = (r1 < Msplit) ? bias0[r1] : bias1[r1 - Msplit];
#pragma unroll
        for (int nt = 0; nt < 4; nt++) {
            const int n = col0 + wn * 32 + nt * 8 + tig * 2;
            const size_t i0 = ((size_t)bz * M + r0) * HW + n;
            const size_t i1 = ((size_t)bz * M + r1) * HW + n;
            const float4 c = acc[mt][nt];
            if (MODE == 0) {
                *(float2*)(Y + i0) = make_float2(c.x + bia0, c.y + bia0);
                *(float2*)(Y + i1) = make_float2(c.z + bia1, c.w + bia1);
            } else {
                const float2 f0 = *(const float2*)(fs + i0);
                const float2 f1 = *(const float2*)(fs + i1);
                const float2 q0 = *(const float2*)(o2 + i0);
                const float2 q1 = *(const float2*)(o2 + i1);
                float v;
                float2 r;
                v = c.x + bia0; r.x = f0.x + q0.x / (1.f + __expf(-v));
                v = c.y + bia0; r.y = f0.y + q0.y / (1.f + __expf(-v));
                *(float2*)(Y + i0) = r;
                v = c.z + bia1; r.x = f1.x + q1.x / (1.f + __expf(-v));
                v = c.w + bia1; r.y = f1.y + q1.y / (1.f + __expf(-v));
                *(float2*)(Y + i1) = r;
            }
        }
    }
}

// ---------------------------------------------------------------------------
// Epipolar attention: one block per (b, head, h). fp32 SIMT (accuracy anchor).
// ---------------------------------------------------------------------------
__global__ __launch_bounds__(256, 1)
void attn_k(const float* __restrict__ q, const float* __restrict__ kv,
            float* __restrict__ ao)
{
    extern __shared__ float sm[];
    float* Qs = sm;                     // [96][128]
    float* Ks = sm + HDIM * WW;         // [96][128] (K, then reused for V)
    float* Ss = sm + 2 * HDIM * WW;     // [128][128]  S[wp][w]
    const int h = blockIdx.x, n = blockIdx.y, b = blockIdx.z;
    const int tid = threadIdx.x;

    const size_t qbase = (((size_t)b * CN + n * HDIM) * HH + h) * WW;
    const size_t kbase = (((size_t)b * 2 * CN + n * HDIM) * HH + h) * WW;
    const size_t vbase = kbase + (size_t)CN * HW;

    {
        const int lane = tid & 31;
        const int r0 = tid >> 5;
#pragma unroll
        for (int it = 0; it < 12; it++) {
            const int cc = r0 + it * 8;
            *(float4*)&Qs[cc * WW + lane * 4] =
                *(const float4*)(q + qbase + (size_t)cc * HW + lane * 4);
            *(float4*)&Ks[cc * WW + lane * 4] =
                *(const float4*)(kv + kbase + (size_t)cc * HW + lane * 4);
        }
    }
    __syncthreads();

    const int tx = tid & 15, ty = tid >> 4;
    {   // GEMM1: S = scale * K^T . Q
        float acc[8][8];
#pragma unroll
        for (int j = 0; j < 8; j++)
#pragma unroll
            for (int i = 0; i < 8; i++) acc[j][i] = 0.f;
#pragma unroll 4
        for (int cc = 0; cc < HDIM; cc++) {
            float qf[8], kf[8];
#pragma unroll
            for (int i = 0; i < 8; i++) qf[i] = Qs[cc * WW + tx + 16 * i];
#pragma unroll
            for (int j = 0; j < 8; j++) kf[j] = Ks[cc * WW + ty + 16 * j];
#pragma unroll
            for (int j = 0; j < 8; j++)
#pragma unroll
                for (int i = 0; i < 8; i++)
                    acc[j][i] = fmaf(kf[j], qf[i], acc[j][i]);
        }
        const float scale = 0.10206207261596575f;  // 1/sqrt(96)
#pragma unroll
        for (int j = 0; j < 8; j++)
#pragma unroll
            for (int i = 0; i < 8; i++)
                Ss[(ty + 16 * j) * WW + tx + 16 * i] = acc[j][i] * scale;
    }
    __syncthreads();

    if (tid < WW) {   // softmax per column w
        const int w = tid;
        float mx = -1e30f;
#pragma unroll 8
        for (int wp = 0; wp < WW; wp++) mx = fmaxf(mx, Ss[wp * WW + w]);
        float s = 0.f;
#pragma unroll 8
        for (int wp = 0; wp < WW; wp++) {
            const float e = __expf(Ss[wp * WW + w] - mx);
            Ss[wp * WW + w] = e;
            s += e;
        }
        const float inv = 1.f / s;
#pragma unroll 8
        for (int wp = 0; wp < WW; wp++) Ss[wp * WW + w] *= inv;
    } else {          // overlap: V load
        const int t = tid - 128;
        const int lane = t & 31;
        const int r0 = t >> 5;
#pragma unroll
        for (int it = 0; it < 24; it++) {
            const int cc = r0 + it * 4;
            *(float4*)&Ks[cc * WW + lane * 4] =
                *(const float4*)(kv + vbase + (size_t)cc * HW + lane * 4);
        }
    }
    __syncthreads();

    {   // GEMM2: out = V . P
        float acc2[6][8];
#pragma unroll
        for (int jc = 0; jc < 6; jc++)
#pragma unroll
            for (int i = 0; i < 8; i++) acc2[jc][i] = 0.f;
#pragma unroll 4
        for (int wp = 0; wp < WW; wp++) {
            float vf[6], pf[8];
#pragma unroll
            for (int jc = 0; jc < 6; jc++) vf[jc] = Ks[(ty + 16 * jc) * WW + wp];
#pragma unroll
            for (int i = 0; i < 8; i++) pf[i] = Ss[wp * WW + tx + 16 * i];
#pragma unroll
            for (int jc = 0; jc < 6; jc++)
#pragma unroll
                for (int i = 0; i < 8; i++)
                    acc2[jc][i] = fmaf(vf[jc], pf[i], acc2[jc][i]);
        }
#pragma unroll
        for (int jc = 0; jc < 6; jc++) {
            const int cc = ty + 16 * jc;
#pragma unroll
            for (int i = 0; i < 8; i++)
                ao[qbase + (size_t)cc * HW + tx + 16 * i] = acc2[jc][i];
        }
    }
}

// ---------------------------------------------------------------------------
// BatchNorm (training-mode batch stats), 3 stages, no atomics
// ---------------------------------------------------------------------------
__global__ __launch_bounds__(256)
void bnstats_k(const float* __restrict__ y)
{
    const int bc = blockIdx.x;
    const float4* p = (const float4*)(y + (size_t)bc * HW);
    const int tid = threadIdx.x;
    float s = 0.f, sq = 0.f;
#pragma unroll
    for (int it = 0; it < 8; it++) {
        const float4 v = p[tid + it * 256];
        s += v.x + v.y + v.z + v.w;
        sq += v.x * v.x + v.y * v.y + v.z * v.z + v.w * v.w;
    }
#pragma unroll
    for (int o = 16; o > 0; o >>= 1) {
        s += __shfl_down_sync(0xffffffffu, s, o);
        sq += __shfl_down_sync(0xffffffffu, sq, o);
    }
    __shared__ float ss[8], sqq[8];
    if ((tid & 31) == 0) { ss[tid >> 5] = s; sqq[tid >> 5] = sq; }
    __syncthreads();
    if (tid == 0) {
        float ts = 0.f, tq = 0.f;
#pragma unroll
        for (int i = 0; i < 8; i++) { ts += ss[i]; tq += sqq[i]; }
        g_psum[bc] = ts;
        g_psq[bc] = tq;
    }
}

__global__ void bnfin_k(const float* __restrict__ gamma,
                        const float* __restrict__ beta)
{
    const int c = threadIdx.x;
    float s = 0.f, sq = 0.f;
#pragma unroll
    for (int b = 0; b < BB; b++) { s += g_psum[b * CN + c]; sq += g_psq[b * CN + c]; }
    const float invN = 1.f / (float)(BB * HW);
    const float mean = s * invN;
    const float var = sq * invN - mean * mean;
    const float inv = rsqrtf(var + 1e-5f);
    const float sc = gamma[c] * inv;
    g_scale[c] = sc;
    g_shift[c] = beta[c] - mean * sc;
}

__global__ void bnapply_k(float* __restrict__ y)
{
    const size_t i = ((size_t)blockIdx.x * 256 + threadIdx.x) * 4;
    const int c = (int)((i >> 13) % CN);
    float4 v = *(float4*)(y + i);
    const float sc = g_scale[c], sh = g_shift[c];
    v.x = v.x * sc + sh;
    v.y = v.y * sc + sh;
    v.z = v.z * sc + sh;
    v.w = v.w * sc + sh;
    *(float4*)(y + i) = v;
}

// ---------------------------------------------------------------------------
extern "C" void kernel_launch(void* const* d_in, const int* in_sizes, int n_in,
                              void* d_out, int out_size)
{
    (void)in_sizes; (void)n_in; (void)out_size;
    const float* fs    = (const float*)d_in[0];
    const float* fo    = (const float*)d_in[1];
    const float* wq    = (const float*)d_in[2];
    const float* bq    = (const float*)d_in[3];
    const float* wk    = (const float*)d_in[4];
    const float* bk    = (const float*)d_in[5];
    const float* wv    = (const float*)d_in[6];
    const float* bv    = (const float*)d_in[7];
    const float* wo    = (const float*)d_in[8];
    const float* bo    = (const float*)d_in[9];
    const float* wg    = (const float*)d_in[10];
    const float* bg    = (const float*)d_in[11];
    const float* gamma = (const float*)d_in[12];
    const float* beta  = (const float*)d_in[13];
    float* out = (float*)d_out;

    float *q, *kvb, *ao, *o2;
    cudaGetSymbolAddress((void**)&q,   g_q);
    cudaGetSymbolAddress((void**)&kvb, g_kv);
    cudaGetSymbolAddress((void**)&ao,  g_ao);
    cudaGetSymbolAddress((void**)&o2,  g_o2);

    const int ATTN_SMEM = (2 * HDIM * WW + WW * WW) * (int)sizeof(float); // 163840
    cudaFuncSetAttribute(attn_k, cudaFuncAttributeMaxDynamicSharedMemorySize, ATTN_SMEM);

    const dim3 blk(256);
    // Q = wq @ feat_self + bq
    gemm_t<0><<<dim3(64, 3, 8), blk>>>(wq, wq, CN, CN, bq, bq,
                                       fs, fs, CN, CN, CN, q, nullptr, nullptr);
    // [K;V] = [wk;wv] @ feat_other + [bk;bv]
    gemm_t<0><<<dim3(64, 6, 8), blk>>>(wk, wv, CN, CN, bk, bv,
                                       fo, fo, CN, 2 * CN, CN, kvb, nullptr, nullptr);
    // epipolar attention per (h, head, b)
    attn_k<<<dim3(HH, NHEAD, BB), blk, ATTN_SMEM>>>(q, kvb, ao);
    // out2 = wo @ attn_out + bo
    gemm_t<0><<<dim3(64, 3, 8), blk>>>(wo, wo, CN, CN, bo, bo,
                                       ao, ao, CN, CN, CN, o2, nullptr, nullptr);
    // fused = fs + sigmoid(wg @ [fs; out2] + bg) * out2  -> d_out
    gemm_t<1><<<dim3(64, 3, 8), blk>>>(wg, wg, CN, 2 * CN, bg, bg,
                                       fs, o2, CN, CN, 2 * CN, out, fs, o2);
    // BatchNorm
    bnstats_k<<<BB * CN, 256>>>(out);
    bnfin_k<<<1, CN>>>(gamma, beta);
    bnapply_k<<<BB * CN * HW / 1024, 256>>>(out);
}

// round 3
// speedup vs baseline: 2.7976x; 1.1685x over previous
#include <cuda_runtime.h>
#include <cstdint>

constexpr int CN = 384;
constexpr int NHEAD = 4;
constexpr int HDIM = 96;
constexpr int HH = 64;
constexpr int WW = 128;
constexpr int HW = HH * WW;   // 8192
constexpr int BB = 8;

// Scratch (device globals: allocation-free, harness-legal)
__device__ float g_q[BB * CN * HW];
__device__ float g_kv[BB * 2 * CN * HW];
__device__ float g_ao[BB * CN * HW];
__device__ float g_o2[BB * CN * HW];
__device__ float g_psum[BB * CN];
__device__ float g_psq[BB * CN];
__device__ float g_scale[CN];
__device__ float g_shift[CN];

__device__ __forceinline__ float to_tf32(float x) {
    uint32_t u;
    asm("cvt.rna.tf32.f32 %0, %1;" : "=r"(u) : "f"(x));
    return __uint_as_float(u);
}

__device__ __forceinline__ void mma_tf32(float4& d, const uint32_t a[4], const uint32_t b[2]) {
    asm volatile(
        "mma.sync.aligned.m16n8k8.row.col.f32.tf32.tf32.f32 "
        "{%0,%1,%2,%3}, {%4,%5,%6,%7}, {%8,%9}, {%0,%1,%2,%3};\n"
        : "+f"(d.x), "+f"(d.y), "+f"(d.z), "+f"(d.w)
        : "r"(a[0]), "r"(a[1]), "r"(a[2]), "r"(a[3]), "r"(b[0]), "r"(b[1]));
}

// ---------------------------------------------------------------------------
// tf32 mma GEMM, block 128(M) x 256(N), K tile 16, 8 warps at 64x64 each.
//   Y[(bz*M + m)*HW + n] = epilogue( sum_c A[m][c] * X[(bz*Cin + c)*HW + n] + bias[m] )
// ---------------------------------------------------------------------------
constexpr int APAD = 20;              // As row stride (floats)
constexpr int BPAD = 264;             // Bs row stride (floats), 264 % 32 == 8
constexpr int ASZ = 128 * APAD;       // 2560 floats / buffer
constexpr int BSZ = 16 * BPAD;        // 4224 floats / buffer
constexpr int GSMEM = (2 * ASZ + 2 * BSZ) * 4;   // 54,272 B

template <int MODE>
__global__ __launch_bounds__(256, 1)
void gemm_t(const float* __restrict__ A0, const float* __restrict__ A1,
            int Msplit, int lda,
            const float* __restrict__ bias0, const float* __restrict__ bias1,
            const float* __restrict__ X0, const float* __restrict__ X1,
            int Ksplit, int M, int K,
            float* __restrict__ Y,
            const float* __restrict__ fs, const float* __restrict__ o2)
{
    extern __shared__ float smg[];
    float* Asb = smg;                 // [2][ASZ]
    float* Bsb = smg + 2 * ASZ;       // [2][BSZ]

    const int tid = threadIdx.x;
    const int lane = tid & 31;
    const int warp = tid >> 5;
    const int group = lane >> 2;      // 0..7
    const int tig = lane & 3;         // 0..3
    const int wm = warp & 1;          // 2 warps in M
    const int wn = warp >> 1;         // 4 warps in N
    const int row0 = blockIdx.y * 128;
    const int col0 = blockIdx.x * 256;
    const int bz = blockIdx.z;
    const int C1 = K - Ksplit;

    // A loader: thread -> (row m_ld, k-half kq)
    const int m_ld = tid >> 1;
    const int kq = (tid & 1) * 8;
    const int mg = row0 + m_ld;
    const float* aptr = (mg < Msplit) ? (A0 + (size_t)mg * lda)
                                      : (A1 + (size_t)(mg - Msplit) * lda);
    // B loader: thread -> k rows {kb, kb+4, kb+8, kb+12}, col quarter
    const int kb = tid >> 6;            // 0..3
    const int nq4 = (tid & 63) * 4;     // 0..252

    float4 acc[4][8];
#pragma unroll
    for (int i = 0; i < 4; i++)
#pragma unroll
        for (int j = 0; j < 8; j++) acc[i][j] = make_float4(0.f, 0.f, 0.f, 0.f);

    const int iters = K >> 4;

    auto xrow = [&](int cg) -> const float* {
        return (cg < Ksplit) ? (X0 + ((size_t)bz * Ksplit + cg) * HW)
                             : (X1 + ((size_t)bz * C1 + (cg - Ksplit)) * HW);
    };

    // ---- prologue ----
    {
        float4 a0 = *(const float4*)(aptr + kq);
        float4 a1 = *(const float4*)(aptr + kq + 4);
        float4 av0 = make_float4(to_tf32(a0.x), to_tf32(a0.y), to_tf32(a0.z), to_tf32(a0.w));
        float4 av1 = make_float4(to_tf32(a1.x), to_tf32(a1.y), to_tf32(a1.z), to_tf32(a1.w));
        *(float4*)&Asb[m_ld * APAD + kq] = av0;
        *(float4*)&Asb[m_ld * APAD + kq + 4] = av1;
#pragma unroll
        for (int j = 0; j < 4; j++) {
            const int kr = kb + 4 * j;
            float4 b = *(const float4*)(xrow(kr) + col0 + nq4);
            *(float4*)&Bsb[kr * BPAD + nq4] =
                make_float4(to_tf32(b.x), to_tf32(b.y), to_tf32(b.z), to_tf32(b.w));
        }
    }
    __syncthreads();

    for (int it = 0; it < iters; it++) {
        const int buf = it & 1;
        float4 pa0, pa1, pb[4];
        const bool more = (it + 1 < iters);
        if (more) {
            const int k0 = (it + 1) << 4;
            pa0 = *(const float4*)(aptr + k0 + kq);
            pa1 = *(const float4*)(aptr + k0 + kq + 4);
#pragma unroll
            for (int j = 0; j < 4; j++)
                pb[j] = *(const float4*)(xrow(k0 + kb + 4 * j) + col0 + nq4);
        }

        const float* Ab = Asb + buf * ASZ;
        const float* Bb = Bsb + buf * BSZ;
#pragma unroll
        for (int kk = 0; kk < 16; kk += 8) {
            uint32_t a[4][4], b[8][2];
#pragma unroll
            for (int mt = 0; mt < 4; mt++) {
                const int r = wm * 64 + mt * 16 + group;
                a[mt][0] = __float_as_uint(Ab[r * APAD + kk + tig]);
                a[mt][1] = __float_as_uint(Ab[(r + 8) * APAD + kk + tig]);
                a[mt][2] = __float_as_uint(Ab[r * APAD + kk + tig + 4]);
                a[mt][3] = __float_as_uint(Ab[(r + 8) * APAD + kk + tig + 4]);
            }
#pragma unroll
            for (int nt = 0; nt < 8; nt++) {
                const int c = wn * 64 + nt * 8 + group;
                b[nt][0] = __float_as_uint(Bb[(kk + tig) * BPAD + c]);
                b[nt][1] = __float_as_uint(Bb[(kk + tig + 4) * BPAD + c]);
            }
#pragma unroll
            for (int mt = 0; mt < 4; mt++)
#pragma unroll
                for (int nt = 0; nt < 8; nt++)
                    mma_tf32(acc[mt][nt], a[mt], b[nt]);
        }

        if (more) {
            float* An = Asb + (buf ^ 1) * ASZ;
            float* Bn = Bsb + (buf ^ 1) * BSZ;
            *(float4*)&An[m_ld * APAD + kq] =
                make_float4(to_tf32(pa0.x), to_tf32(pa0.y), to_tf32(pa0.z), to_tf32(pa0.w));
            *(float4*)&An[m_ld * APAD + kq + 4] =
                make_float4(to_tf32(pa1.x), to_tf32(pa1.y), to_tf32(pa1.z), to_tf32(pa1.w));
#pragma unroll
            for (int j = 0; j < 4; j++) {
                const int kr = kb + 4 * j;
                *(float4*)&Bn[kr * BPAD + nq4] =
                    make_float4(to_tf32(pb[j].x), to_tf32(pb[j].y), to_tf32(pb[j].z), to_tf32(pb[j].w));
            }
        }
        __syncthreads();
    }

    // ---- epilogue ----
#pragma unroll
    for (int mt = 0; mt < 4; mt++) {
        const int r0 = row0 + wm * 64 + mt * 16 + group;
        const int r1 = r0 + 8;
        const float bia0 = (r0 < Msplit) ? bias0[r0] : bias1[r0 - Msplit];
        const float bia1 = (r1 < Msplit) ? bias0[r1] : bias1[r1 - Msplit];
#pragma unroll
        for (int nt = 0; nt < 8; nt++) {
            const int n = col0 + wn * 64 + nt * 8 + tig * 2;
            const size_t i0 = ((size_t)bz * M + r0) * HW + n;
            const size_t i1 = ((size_t)bz * M + r1) * HW + n;
            const float4 c = acc[mt][nt];
            if (MODE == 0) {
                *(float2*)(Y + i0) = make_float2(c.x + bia0, c.y + bia0);
                *(float2*)(Y + i1) = make_float2(c.z + bia1, c.w + bia1);
            } else {
                const float2 f0 = *(const float2*)(fs + i0);
                const float2 f1 = *(const float2*)(fs + i1);
                const float2 q0 = *(const float2*)(o2 + i0);
                const float2 q1 = *(const float2*)(o2 + i1);
                float v; float2 r;
                v = c.x + bia0; r.x = f0.x + q0.x / (1.f + __expf(-v));
                v = c.y + bia0; r.y = f0.y + q0.y / (1.f + __expf(-v));
                *(float2*)(Y + i0) = r;
                v = c.z + bia1; r.x = f1.x + q1.x / (1.f + __expf(-v));
                v = c.w + bia1; r.y = f1.y + q1.y / (1.f + __expf(-v));
                *(float2*)(Y + i1) = r;
            }
        }
    }
}

// ---------------------------------------------------------------------------
// Epipolar attention, tensorized. One block per (h, head, b), 256 threads.
// smem strides 136 (8 mod 32) -> all frag patterns conflict-free.
// ---------------------------------------------------------------------------
constexpr int SP = 136;
constexpr int ATT_SMEM = (HDIM + HDIM + WW) * SP * 4;  // 174,080 B

__global__ __launch_bounds__(256, 1)
void attn_k(const float* __restrict__ q, const float* __restrict__ kv,
            float* __restrict__ ao)
{
    extern __shared__ float sm[];
    float* Qs = sm;                 // [96][136]
    float* Ks = sm + HDIM * SP;     // [96][136] K, then V
    float* Ss = sm + 2 * HDIM * SP; // [128][136] S[wp][w]
    const int h = blockIdx.x, n = blockIdx.y, b = blockIdx.z;
    const int tid = threadIdx.x;
    const int lane = tid & 31;
    const int warp = tid >> 5;
    const int group = lane >> 2;
    const int tig = lane & 3;

    const size_t qbase = (((size_t)b * CN + n * HDIM) * HH + h) * WW;
    const size_t kbase = (((size_t)b * 2 * CN + n * HDIM) * HH + h) * WW;
    const size_t vbase = kbase + (size_t)CN * HW;

    {   // load Q, K tiles with tf32 rounding
        const int l4 = lane * 4;
#pragma unroll
        for (int it = 0; it < 12; it++) {
            const int cc = warp + it * 8;
            float4 a = *(const float4*)(q + qbase + (size_t)cc * HW + l4);
            float4 c = *(const float4*)(kv + kbase + (size_t)cc * HW + l4);
            *(float4*)&Qs[cc * SP + l4] =
                make_float4(to_tf32(a.x), to_tf32(a.y), to_tf32(a.z), to_tf32(a.w));
            *(float4*)&Ks[cc * SP + l4] =
                make_float4(to_tf32(c.x), to_tf32(c.y), to_tf32(c.z), to_tf32(c.w));
        }
    }
    __syncthreads();

    {   // GEMM1: S[wp][w] = scale * sum_cc K[cc][wp] * Q[cc][w]
        // warps 2(m=wp) x 4(n=w), warp tile 64x32
        const int wm = warp & 1, wn = warp >> 1;
        float4 acc[4][4];
#pragma unroll
        for (int i = 0; i < 4; i++)
#pragma unroll
            for (int j = 0; j < 4; j++) acc[i][j] = make_float4(0.f, 0.f, 0.f, 0.f);
#pragma unroll
        for (int kk = 0; kk < HDIM; kk += 8) {
            uint32_t a[4][4], bfr[4][2];
#pragma unroll
            for (int mt = 0; mt < 4; mt++) {
                const int wp = wm * 64 + mt * 16 + group;
                a[mt][0] = __float_as_uint(Ks[(kk + tig) * SP + wp]);
                a[mt][1] = __float_as_uint(Ks[(kk + tig) * SP + wp + 8]);
                a[mt][2] = __float_as_uint(Ks[(kk + tig + 4) * SP + wp]);
                a[mt][3] = __float_as_uint(Ks[(kk + tig + 4) * SP + wp + 8]);
            }
#pragma unroll
            for (int nt = 0; nt < 4; nt++) {
                const int w = wn * 32 + nt * 8 + group;
                bfr[nt][0] = __float_as_uint(Qs[(kk + tig) * SP + w]);
                bfr[nt][1] = __float_as_uint(Qs[(kk + tig + 4) * SP + w]);
            }
#pragma unroll
            for (int mt = 0; mt < 4; mt++)
#pragma unroll
                for (int nt = 0; nt < 4; nt++)
                    mma_tf32(acc[mt][nt], a[mt], bfr[nt]);
        }
        const float scale = 0.10206207261596575f;  // 1/sqrt(96)
#pragma unroll
        for (int mt = 0; mt < 4; mt++) {
            const int wp = wm * 64 + mt * 16 + group;
#pragma unroll
            for (int nt = 0; nt < 4; nt++) {
                const int w = wn * 32 + nt * 8 + tig * 2;
                const float4 c = acc[mt][nt];
                *(float2*)&Ss[wp * SP + w] = make_float2(c.x * scale, c.y * scale);
                *(float2*)&Ss[(wp + 8) * SP + w] = make_float2(c.z * scale, c.w * scale);
            }
        }
    }
    __syncthreads();

    if (tid < WW) {   // softmax over wp for column w; store P as tf32
        const int w = tid;
        float mx = -1e30f;
#pragma unroll 8
        for (int wp = 0; wp < WW; wp++) mx = fmaxf(mx, Ss[wp * SP + w]);
        float s = 0.f;
#pragma unroll 8
        for (int wp = 0; wp < WW; wp++) {
            const float e = __expf(Ss[wp * SP + w] - mx);
            Ss[wp * SP + w] = e;
            s += e;
        }
        const float inv = 1.f / s;
#pragma unroll 8
        for (int wp = 0; wp < WW; wp++) Ss[wp * SP + w] = to_tf32(Ss[wp * SP + w] * inv);
    } else {          // overlap: V load (tf32)
        const int t = tid - 128;
        const int l4 = (t & 31) * 4;
        const int r0 = t >> 5;
#pragma unroll
        for (int it = 0; it < 24; it++) {
            const int cc = r0 + it * 4;
            float4 c = *(const float4*)(kv + vbase + (size_t)cc * HW + l4);
            *(float4*)&Ks[cc * SP + l4] =
                make_float4(to_tf32(c.x), to_tf32(c.y), to_tf32(c.z), to_tf32(c.w));
        }
    }
    __syncthreads();

    if (warp < 6) {   // GEMM2: out[cc][w] = sum_wp V[cc][wp] * P[wp][w]
        const int m0 = warp * 16;   // 6 warps x 16 rows = 96
        float4 acc[16];
#pragma unroll
        for (int j = 0; j < 16; j++) acc[j] = make_float4(0.f, 0.f, 0.f, 0.f);
#pragma unroll 4
        for (int kk = 0; kk < WW; kk += 8) {
            uint32_t a[4], bfr[16][2];
            a[0] = __float_as_uint(Ks[(m0 + group) * SP + kk + tig]);
            a[1] = __float_as_uint(Ks[(m0 + group + 8) * SP + kk + tig]);
            a[2] = __float_as_uint(Ks[(m0 + group) * SP + kk + tig + 4]);
            a[3] = __float_as_uint(Ks[(m0 + group + 8) * SP + kk + tig + 4]);
#pragma unroll
            for (int nt = 0; nt < 16; nt++) {
                const int w = nt * 8 + group;
                bfr[nt][0] = __float_as_uint(Ss[(kk + tig) * SP + w]);
                bfr[nt][1] = __float_as_uint(Ss[(kk + tig + 4) * SP + w]);
            }
#pragma unroll
            for (int nt = 0; nt < 16; nt++)
                mma_tf32(acc[nt], a, bfr[nt]);
        }
#pragma unroll
        for (int nt = 0; nt < 16; nt++) {
            const int w = nt * 8 + tig * 2;
            const float4 c = acc[nt];
            *(float2*)(ao + qbase + (size_t)(m0 + group) * HW + w) = make_float2(c.x, c.y);
            *(float2*)(ao + qbase + (size_t)(m0 + group + 8) * HW + w) = make_float2(c.z, c.w);
        }
    }
}

// ---------------------------------------------------------------------------
// BatchNorm (training-mode batch stats), 3 stages, no atomics
// ---------------------------------------------------------------------------
__global__ __launch_bounds__(256)
void bnstats_k(const float* __restrict__ y)
{
    const int bc = blockIdx.x;
    const float4* p = (const float4*)(y + (size_t)bc * HW);
    const int tid = threadIdx.x;
    float s = 0.f, sq = 0.f;
#pragma unroll
    for (int it = 0; it < 8; it++) {
        const float4 v = p[tid + it * 256];
        s += v.x + v.y + v.z + v.w;
        sq += v.x * v.x + v.y * v.y + v.z * v.z + v.w * v.w;
    }
#pragma unroll
    for (int o = 16; o > 0; o >>= 1) {
        s += __shfl_down_sync(0xffffffffu, s, o);
        sq += __shfl_down_sync(0xffffffffu, sq, o);
    }
    __shared__ float ss[8], sqq[8];
    if ((tid & 31) == 0) { ss[tid >> 5] = s; sqq[tid >> 5] = sq; }
    __syncthreads();
    if (tid == 0) {
        float ts = 0.f, tq = 0.f;
#pragma unroll
        for (int i = 0; i < 8; i++) { ts += ss[i]; tq += sqq[i]; }
        g_psum[bc] = ts;
        g_psq[bc] = tq;
    }
}

__global__ void bnfin_k(const float* __restrict__ gamma,
                        const float* __restrict__ beta)
{
    const int c = threadIdx.x;
    float s = 0.f, sq = 0.f;
#pragma unroll
    for (int b = 0; b < BB; b++) { s += g_psum[b * CN + c]; sq += g_psq[b * CN + c]; }
    const float invN = 1.f / (float)(BB * HW);
    const float mean = s * invN;
    const float var = sq * invN - mean * mean;
    const float inv = rsqrtf(var + 1e-5f);
    const float sc = gamma[c] * inv;
    g_scale[c] = sc;
    g_shift[c] = beta[c] - mean * sc;
}

__global__ void bnapply_k(float* __restrict__ y)
{
    const size_t i = ((size_t)blockIdx.x * 256 + threadIdx.x) * 4;
    const int c = (int)((i >> 13) % CN);
    float4 v = *(float4*)(y + i);
    const float sc = g_scale[c], sh = g_shift[c];
    v.x = v.x * sc + sh;
    v.y = v.y * sc + sh;
    v.z = v.z * sc + sh;
    v.w = v.w * sc + sh;
    *(float4*)(y + i) = v;
}

// ---------------------------------------------------------------------------
extern "C" void kernel_launch(void* const* d_in, const int* in_sizes, int n_in,
                              void* d_out, int out_size)
{
    (void)in_sizes; (void)n_in; (void)out_size;
    const float* fs    = (const float*)d_in[0];
    const float* fo    = (const float*)d_in[1];
    const float* wq    = (const float*)d_in[2];
    const float* bq    = (const float*)d_in[3];
    const float* wk    = (const float*)d_in[4];
    const float* bk    = (const float*)d_in[5];
    const float* wv    = (const float*)d_in[6];
    const float* bv    = (const float*)d_in[7];
    const float* wo    = (const float*)d_in[8];
    const float* bo    = (const float*)d_in[9];
    const float* wg    = (const float*)d_in[10];
    const float* bg    = (const float*)d_in[11];
    const float* gamma = (const float*)d_in[12];
    const float* beta  = (const float*)d_in[13];
    float* out = (float*)d_out;

    float *q, *kvb, *ao, *o2;
    cudaGetSymbolAddress((void**)&q,   g_q);
    cudaGetSymbolAddress((void**)&kvb, g_kv);
    cudaGetSymbolAddress((void**)&ao,  g_ao);
    cudaGetSymbolAddress((void**)&o2,  g_o2);

    cudaFuncSetAttribute(gemm_t<0>, cudaFuncAttributeMaxDynamicSharedMemorySize, GSMEM);
    cudaFuncSetAttribute(gemm_t<1>, cudaFuncAttributeMaxDynamicSharedMemorySize, GSMEM);
    cudaFuncSetAttribute(attn_k, cudaFuncAttributeMaxDynamicSharedMemorySize, ATT_SMEM);

    const dim3 blk(256);
    gemm_t<0><<<dim3(32, 3, 8), blk, GSMEM>>>(wq, wq, CN, CN, bq, bq,
                                              fs, fs, CN, CN, CN, q, nullptr, nullptr);
    gemm_t<0><<<dim3(32, 6, 8), blk, GSMEM>>>(wk, wv, CN, CN, bk, bv,
                                              fo, fo, CN, 2 * CN, CN, kvb, nullptr, nullptr);
    attn_k<<<dim3(HH, NHEAD, BB), blk, ATT_SMEM>>>(q, kvb, ao);
    gemm_t<0><<<dim3(32, 3, 8), blk, GSMEM>>>(wo, wo, CN, CN, bo, bo,
                                              ao, ao, CN, CN, CN, o2, nullptr, nullptr);
    gemm_t<1><<<dim3(32, 3, 8), blk, GSMEM>>>(wg, wg, CN, 2 * CN, bg, bg,
                                              fs, o2, CN, CN, 2 * CN, out, fs, o2);
    bnstats_k<<<BB * CN, 256>>>(out);
    bnfin_k<<<1, CN>>>(gamma, beta);
    bnapply_k<<<BB * CN * HW / 1024, 256>>>(out);
}